// round 2
// baseline (speedup 1.0000x reference)
#include <cuda_runtime.h>
#include <cstdint>

#define N_EDGES 3200000
#define N_NODES 100000

__global__ __launch_bounds__(256)
void sh_edge_attrs_kernel(const float* __restrict__ pos,
                          const void* __restrict__ edge_index_raw,
                          const float* __restrict__ shift,
                          float* __restrict__ out)
{
    const int e = blockIdx.x * blockDim.x + threadIdx.x;
    if (e >= N_EDGES) return;

    // --- dtype probe: int64 indices (<2^32) have zero high halves ---
    const unsigned long long* p64 = (const unsigned long long*)edge_index_raw;
    const bool is64 = (((p64[0] | p64[1] | p64[2] | p64[3]) >> 32) == 0ULL);

    long long src, dst;
    if (is64) {
        const long long* ei = (const long long*)edge_index_raw;
        src = ei[e];
        dst = ei[N_EDGES + e];
    } else {
        const int* ei = (const int*)edge_index_raw;
        src = ei[e];
        dst = ei[N_EDGES + e];
    }
    // defensive clamp (no-op when inputs are as expected)
    src = min((long long)(N_NODES - 1), max(0LL, src));
    dst = min((long long)(N_NODES - 1), max(0LL, dst));

    // pos gathers (pos is 1.2MB -> L2 resident)
    const float pxd = pos[dst * 3 + 0];
    const float pyd = pos[dst * 3 + 1];
    const float pzd = pos[dst * 3 + 2];
    const float pxs = pos[src * 3 + 0];
    const float pys = pos[src * 3 + 1];
    const float pzs = pos[src * 3 + 2];

    const float sx = shift[e * 3 + 0];
    const float sy = shift[e * 3 + 1];
    const float sz = shift[e * 3 + 2];

    const float vx = pxd - pxs - sx;
    const float vy = pyd - pys - sy;
    const float vz = pzd - pzs - sz;

    const float n2   = vx * vx + vy * vy + vz * vz;
    const float rinv = rsqrtf(n2);
    const float len  = n2 * rinv;    // sqrt(n2)

    const float x = vx * rinv;
    const float y = vy * rinv;
    const float z = vz * rinv;

    const float SQRT3 = 1.7320508075688772f;
    const float SQRT5 = 2.2360679774997896f;

    const float x2 = x * x, y2 = y * y, z2 = z * z;

    const float sh1_0 = SQRT3 * x;
    const float sh1_1 = SQRT3 * y;
    const float sh1_2 = SQRT3 * z;

    const float sh2_0 = SQRT5 * (SQRT3 * x * z);
    const float sh2_1 = SQRT5 * (SQRT3 * x * y);
    const float sh2_2 = SQRT5 * (y2 - 0.5f * (x2 + z2));
    const float sh2_3 = SQRT5 * (SQRT3 * y * z);
    const float sh2_4 = SQRT5 * (0.5f * SQRT3 * (z2 - x2));

    // Output: [0,3E) edge_vec | [3E,4E) edge_length | [4E,13E) edge_sh
    float* out_vec = out;
    float* out_len = out + 3LL * N_EDGES;
    float* out_sh  = out + 4LL * N_EDGES;

    out_vec[e * 3 + 0] = vx;
    out_vec[e * 3 + 1] = vy;
    out_vec[e * 3 + 2] = vz;

    out_len[e] = len;

    float* sh = out_sh + (long long)e * 9;
    sh[0] = 1.0f;
    sh[1] = sh1_0;
    sh[2] = sh1_1;
    sh[3] = sh1_2;
    sh[4] = sh2_0;
    sh[5] = sh2_1;
    sh[6] = sh2_2;
    sh[7] = sh2_3;
    sh[8] = sh2_4;
}

extern "C" void kernel_launch(void* const* d_in, const int* in_sizes, int n_in,
                              void* d_out, int out_size)
{
    // Identify inputs by element count (robust to metadata ordering):
    //   pos: 300000 floats, edge_index: 6400000 ints, shift: 9600000 floats
    const float* pos        = nullptr;
    const void*  edge_index = nullptr;
    const float* shift      = nullptr;

    for (int i = 0; i < n_in; i++) {
        if (in_sizes[i] == 3 * N_NODES)      pos        = (const float*)d_in[i];
        else if (in_sizes[i] == 2 * N_EDGES) edge_index = (const void*)d_in[i];
        else if (in_sizes[i] == 3 * N_EDGES) shift      = (const float*)d_in[i];
    }

    float* out = (float*)d_out;

    const int threads = 256;
    const int blocks  = (N_EDGES + threads - 1) / threads;
    sh_edge_attrs_kernel<<<blocks, threads>>>(pos, edge_index, shift, out);
}

// round 3
// speedup vs baseline: 1.7827x; 1.7827x over previous
#include <cuda_runtime.h>
#include <cstdint>

#define N_EDGES 3200000
#define N_NODES 100000
#define EPB 256   // edges per block

__global__ __launch_bounds__(256)
void sh_edge_attrs_kernel(const float* __restrict__ pos,
                          const void* __restrict__ edge_index_raw,
                          const float* __restrict__ shift,
                          float* __restrict__ out)
{
    __shared__ float s_shift[EPB * 3];   // 3072 B
    __shared__ float s_vec[EPB * 3];     // 3072 B
    __shared__ float s_len[EPB];         // 1024 B
    __shared__ float s_sh[EPB * 9];      // 9216 B

    const int t  = threadIdx.x;
    const long long blk_base = (long long)blockIdx.x * EPB;
    const long long e = blk_base + t;

    // ---- stage shift slice: 192 float4 coalesced ----
    {
        const float4* gshift = (const float4*)(shift + blk_base * 3);
        if (t < (EPB * 3) / 4) {
            ((float4*)s_shift)[t] = gshift[t];
        }
    }

    // ---- edge indices (dtype probe: int64 values < 2^32 have zero high halves) ----
    const unsigned long long* p64 = (const unsigned long long*)edge_index_raw;
    const bool is64 = (((p64[0] | p64[1] | p64[2] | p64[3]) >> 32) == 0ULL);

    long long src, dst;
    if (is64) {
        const long long* ei = (const long long*)edge_index_raw;
        src = ei[e];
        dst = ei[N_EDGES + e];
    } else {
        const int* ei = (const int*)edge_index_raw;
        src = ei[e];
        dst = ei[N_EDGES + e];
    }
    src = min((long long)(N_NODES - 1), max(0LL, src));
    dst = min((long long)(N_NODES - 1), max(0LL, dst));

    // ---- pos gathers (L2-resident, latency hidden by occupancy) ----
    const float pxd = __ldg(&pos[dst * 3 + 0]);
    const float pyd = __ldg(&pos[dst * 3 + 1]);
    const float pzd = __ldg(&pos[dst * 3 + 2]);
    const float pxs = __ldg(&pos[src * 3 + 0]);
    const float pys = __ldg(&pos[src * 3 + 1]);
    const float pzs = __ldg(&pos[src * 3 + 2]);

    __syncthreads();   // s_shift ready

    const float sx = s_shift[t * 3 + 0];
    const float sy = s_shift[t * 3 + 1];
    const float sz = s_shift[t * 3 + 2];

    const float vx = pxd - pxs - sx;
    const float vy = pyd - pys - sy;
    const float vz = pzd - pzs - sz;

    const float n2   = vx * vx + vy * vy + vz * vz;
    const float rinv = rsqrtf(n2);
    const float len  = n2 * rinv;

    const float x = vx * rinv;
    const float y = vy * rinv;
    const float z = vz * rinv;

    const float SQRT3 = 1.7320508075688772f;
    const float SQRT5 = 2.2360679774997896f;
    const float x2 = x * x, y2 = y * y, z2 = z * z;

    // ---- stage results in smem (odd strides -> bank-conflict-free) ----
    s_vec[t * 3 + 0] = vx;
    s_vec[t * 3 + 1] = vy;
    s_vec[t * 3 + 2] = vz;
    s_len[t] = len;

    s_sh[t * 9 + 0] = 1.0f;
    s_sh[t * 9 + 1] = SQRT3 * x;
    s_sh[t * 9 + 2] = SQRT3 * y;
    s_sh[t * 9 + 3] = SQRT3 * z;
    s_sh[t * 9 + 4] = SQRT5 * (SQRT3 * x * z);
    s_sh[t * 9 + 5] = SQRT5 * (SQRT3 * x * y);
    s_sh[t * 9 + 6] = SQRT5 * (y2 - 0.5f * (x2 + z2));
    s_sh[t * 9 + 7] = SQRT5 * (SQRT3 * y * z);
    s_sh[t * 9 + 8] = SQRT5 * (0.5f * SQRT3 * (z2 - x2));

    __syncthreads();

    // ---- coalesced float4 stores ----
    // vec region: [0, 3E), block slice = 768 floats = 192 float4
    {
        float4* gvec = (float4*)(out + blk_base * 3);
        if (t < 192) gvec[t] = ((const float4*)s_vec)[t];
    }
    // len region: [3E, 4E), block slice = 256 floats = 64 float4
    {
        float4* glen = (float4*)(out + 3LL * N_EDGES + blk_base);
        if (t < 64) glen[t] = ((const float4*)s_len)[t];
    }
    // sh region: [4E, 13E), block slice = 2304 floats = 576 float4
    {
        float4* gsh = (float4*)(out + 4LL * N_EDGES + blk_base * 9);
        const float4* ssh = (const float4*)s_sh;
        gsh[t]       = ssh[t];
        gsh[t + 256] = ssh[t + 256];
        if (t < 64) gsh[t + 512] = ssh[t + 512];
    }
}

extern "C" void kernel_launch(void* const* d_in, const int* in_sizes, int n_in,
                              void* d_out, int out_size)
{
    // Identify inputs by element count (robust to metadata ordering):
    //   pos: 300000 floats, edge_index: 6400000 ints, shift: 9600000 floats
    const float* pos        = nullptr;
    const void*  edge_index = nullptr;
    const float* shift      = nullptr;

    for (int i = 0; i < n_in; i++) {
        if (in_sizes[i] == 3 * N_NODES)      pos        = (const float*)d_in[i];
        else if (in_sizes[i] == 2 * N_EDGES) edge_index = (const void*)d_in[i];
        else if (in_sizes[i] == 3 * N_EDGES) shift      = (const float*)d_in[i];
    }

    float* out = (float*)d_out;

    const int blocks = N_EDGES / EPB;   // 12500, exact
    sh_edge_attrs_kernel<<<blocks, EPB>>>(pos, edge_index, shift, out);
}

// round 4
// speedup vs baseline: 2.0100x; 1.1275x over previous
#include <cuda_runtime.h>
#include <cstdint>

#define N_EDGES 3200000
#define N_NODES 100000
#define EPB 256   // edges per block

// 16B-aligned padded copy of pos: one LDG.128 per gather instead of 3 LDG.32.
__device__ float4 g_pos_pad[N_NODES];

__global__ __launch_bounds__(256)
void pos_pad_kernel(const float* __restrict__ pos)
{
    const int i = blockIdx.x * blockDim.x + threadIdx.x;
    if (i < N_NODES) {
        g_pos_pad[i] = make_float4(pos[i * 3 + 0], pos[i * 3 + 1], pos[i * 3 + 2], 0.0f);
    }
}

__global__ __launch_bounds__(256)
void sh_edge_attrs_kernel(const void* __restrict__ edge_index_raw,
                          const float* __restrict__ shift,
                          float* __restrict__ out)
{
    __shared__ float s_shift[EPB * 3];   // 3072 B
    __shared__ float s_vec[EPB * 3];     // 3072 B
    __shared__ float s_len[EPB];         // 1024 B
    __shared__ float s_sh[EPB * 9];      // 9216 B

    const int t  = threadIdx.x;
    const long long blk_base = (long long)blockIdx.x * EPB;
    const long long e = blk_base + t;

    // ---- stage shift slice: 192 float4 coalesced ----
    {
        const float4* gshift = (const float4*)(shift + blk_base * 3);
        if (t < (EPB * 3) / 4) {
            ((float4*)s_shift)[t] = gshift[t];
        }
    }

    // ---- edge indices (dtype probe: int64 values < 2^32 have zero high halves) ----
    const unsigned long long* p64 = (const unsigned long long*)edge_index_raw;
    const bool is64 = (((p64[0] | p64[1] | p64[2] | p64[3]) >> 32) == 0ULL);

    int src, dst;
    if (is64) {
        const long long* ei = (const long long*)edge_index_raw;
        src = (int)ei[e];
        dst = (int)ei[N_EDGES + e];
    } else {
        const int* ei = (const int*)edge_index_raw;
        src = ei[e];
        dst = ei[N_EDGES + e];
    }
    src = min(N_NODES - 1, max(0, src));
    dst = min(N_NODES - 1, max(0, dst));

    // ---- pos gathers: single 16B load per node ----
    const float4 pd = __ldg(&g_pos_pad[dst]);
    const float4 ps = __ldg(&g_pos_pad[src]);

    __syncthreads();   // s_shift ready

    const float sx = s_shift[t * 3 + 0];
    const float sy = s_shift[t * 3 + 1];
    const float sz = s_shift[t * 3 + 2];

    const float vx = pd.x - ps.x - sx;
    const float vy = pd.y - ps.y - sy;
    const float vz = pd.z - ps.z - sz;

    const float n2   = vx * vx + vy * vy + vz * vz;
    const float rinv = rsqrtf(n2);
    const float len  = n2 * rinv;

    const float x = vx * rinv;
    const float y = vy * rinv;
    const float z = vz * rinv;

    const float SQRT3 = 1.7320508075688772f;
    const float SQRT5 = 2.2360679774997896f;
    const float x2 = x * x, y2 = y * y, z2 = z * z;

    // ---- stage results in smem (odd strides -> bank-conflict-free) ----
    s_vec[t * 3 + 0] = vx;
    s_vec[t * 3 + 1] = vy;
    s_vec[t * 3 + 2] = vz;
    s_len[t] = len;

    s_sh[t * 9 + 0] = 1.0f;
    s_sh[t * 9 + 1] = SQRT3 * x;
    s_sh[t * 9 + 2] = SQRT3 * y;
    s_sh[t * 9 + 3] = SQRT3 * z;
    s_sh[t * 9 + 4] = SQRT5 * (SQRT3 * x * z);
    s_sh[t * 9 + 5] = SQRT5 * (SQRT3 * x * y);
    s_sh[t * 9 + 6] = SQRT5 * (y2 - 0.5f * (x2 + z2));
    s_sh[t * 9 + 7] = SQRT5 * (SQRT3 * y * z);
    s_sh[t * 9 + 8] = SQRT5 * (0.5f * SQRT3 * (z2 - x2));

    __syncthreads();

    // ---- coalesced float4 stores ----
    // vec region: [0, 3E), block slice = 768 floats = 192 float4
    {
        float4* gvec = (float4*)(out + blk_base * 3);
        if (t < 192) gvec[t] = ((const float4*)s_vec)[t];
    }
    // len region: [3E, 4E), block slice = 256 floats = 64 float4
    {
        float4* glen = (float4*)(out + 3LL * N_EDGES + blk_base);
        if (t < 64) glen[t] = ((const float4*)s_len)[t];
    }
    // sh region: [4E, 13E), block slice = 2304 floats = 576 float4
    {
        float4* gsh = (float4*)(out + 4LL * N_EDGES + blk_base * 9);
        const float4* ssh = (const float4*)s_sh;
        gsh[t]       = ssh[t];
        gsh[t + 256] = ssh[t + 256];
        if (t < 64) gsh[t + 512] = ssh[t + 512];
    }
}

extern "C" void kernel_launch(void* const* d_in, const int* in_sizes, int n_in,
                              void* d_out, int out_size)
{
    // Identify inputs by element count (robust to metadata ordering):
    //   pos: 300000 floats, edge_index: 6400000 ints, shift: 9600000 floats
    const float* pos        = nullptr;
    const void*  edge_index = nullptr;
    const float* shift      = nullptr;

    for (int i = 0; i < n_in; i++) {
        if (in_sizes[i] == 3 * N_NODES)      pos        = (const float*)d_in[i];
        else if (in_sizes[i] == 2 * N_EDGES) edge_index = (const void*)d_in[i];
        else if (in_sizes[i] == 3 * N_EDGES) shift      = (const float*)d_in[i];
    }

    float* out = (float*)d_out;

    pos_pad_kernel<<<(N_NODES + 255) / 256, 256>>>(pos);

    const int blocks = N_EDGES / EPB;   // 12500, exact
    sh_edge_attrs_kernel<<<blocks, EPB>>>(edge_index, shift, out);
}